// round 13
// baseline (speedup 1.0000x reference)
#include <cuda_runtime.h>
#include <cstdint>

#define BB   2
#define NN   8192
#define CIN  64
#define CCAT 67
#define KK   16
#define H1   32
#define H2   64
#define COUT 64

#define GRID 12           // 12x12x12 cells (~4.7 pts/cell)
#define NCELL (GRID*GRID*GRID)
#define CS   (1.0f/12.0f) // cell size

#define SLC  8            // candidate slices per query

typedef unsigned long long u64;

__device__ int    g_knn[BB * NN * KK];
__device__ int    g_cnt[BB * NCELL];          // zero-initialized; scan resets it
__device__ int    g_pack[BB * NN];            // (cell<<13)|rank from bin
__device__ int    g_start[BB * (NCELL + 1)];
__device__ float4 g_sorted[BB * NN];          // (x, y, z, |c|^2)
__device__ int    g_sidx[BB * NN];            // original point index
__device__ float  g_W[COUT * 68];             // collapsed MLP matrix, col 67 = 0
__device__ float  g_C1[COUT];                 // 16 * B
__device__ float  g_C2[COUT];                 // sum(aggr_w) * B + aggr_b

__device__ __forceinline__ int cell_of(float x, float y, float z) {
    int ix = min(GRID - 1, max(0, (int)(x * (float)GRID)));
    int iy = min(GRID - 1, max(0, (int)(y * (float)GRID)));
    int iz = min(GRID - 1, max(0, (int)(z * (float)GRID)));
    return (iz * GRID + iy) * GRID + ix;
}

// ---------------------------------------------------------------------------
// Collapse the affine MLP:  W = w3*w2*w1,  B = w3*(w2*b1 + b2) + b3
// ---------------------------------------------------------------------------
__device__ void precomp_body(
    const float* __restrict__ w1, const float* __restrict__ b1,
    const float* __restrict__ w2, const float* __restrict__ b2,
    const float* __restrict__ w3, const float* __restrict__ b3,
    const float* __restrict__ aggr_w, const float* __restrict__ aggr_b)
{
    __shared__ float s0[4192];       // w1(2144)+w2(2048); later reused for w3(4096)
    __shared__ float s21[64 * 67];   // w2*w1
    __shared__ float st[64];         // w2*b1 + b2
    __shared__ float s_sumU;
    float* sw1 = s0;
    float* sw2 = s0 + 2144;
    const int t = threadIdx.x;
    for (int i = t; i < 2144; i += 256) sw1[i] = w1[i];
    for (int i = t; i < 2048; i += 256) sw2[i] = w2[i];
    if (t == 0) {
        float s = 0.f;
        for (int k = 0; k < KK; k++) s += aggr_w[k];
        s_sumU = s;
    }
    __syncthreads();
    if (t < 64) {
        float acc = b2[t];
        for (int j = 0; j < 32; j++) acc = fmaf(sw2[t * 32 + j], b1[j], acc);
        st[t] = acc;
    }
    for (int i = t; i < 64 * 67; i += 256) {
        int o = i / 67, c = i % 67;
        float acc = 0.f;
        for (int j = 0; j < 32; j++) acc = fmaf(sw2[o * 32 + j], sw1[j * 67 + c], acc);
        s21[i] = acc;
    }
    __syncthreads();
    float* sw3 = s0;                 // overlay (w1/w2 dead)
    for (int i = t; i < 4096; i += 256) sw3[i] = w3[i];
    __syncthreads();
    for (int i = t; i < 64 * 68; i += 256) {
        int o = i / 68, c = i % 68;
        float acc = 0.f;
        if (c < 67)
            for (int j = 0; j < 64; j++) acc = fmaf(sw3[o * 64 + j], s21[j * 67 + c], acc);
        g_W[i] = acc;                // col 67 stays 0 (pad)
    }
    if (t < 64) {
        float B = b3[t];
        for (int j = 0; j < 64; j++) B = fmaf(sw3[t * 64 + j], st[j], B);
        g_C1[t] = 16.0f * B;
        g_C2[t] = fmaf(s_sumU, B, aggr_b[0]);
    }
}

// bin (blocks 0..63) + precomp (block 64)
__global__ __launch_bounds__(256) void knn_bin_pre(
    const float* __restrict__ coords,
    const float* __restrict__ w1, const float* __restrict__ b1,
    const float* __restrict__ w2, const float* __restrict__ b2,
    const float* __restrict__ w3, const float* __restrict__ b3,
    const float* __restrict__ aggr_w, const float* __restrict__ aggr_b)
{
    if (blockIdx.x == 64) {
        precomp_body(w1, b1, w2, b2, w3, b3, aggr_w, aggr_b);
        return;
    }
    const int t = blockIdx.x * 256 + threadIdx.x;
    const int b = t >> 13, q = t & (NN - 1);
    const float* cp = coords + ((size_t)b * NN + q) * 3;
    const int c = cell_of(cp[0], cp[1], cp[2]);
    const int rank = atomicAdd(&g_cnt[b * NCELL + c], 1);
    g_pack[t] = (c << 13) | rank;
}

// prefix-sum over 1728 cells: 864 threads x 2 cells each
__global__ __launch_bounds__(NCELL / 2) void knn_scan() {
    __shared__ int s[NCELL / 2];
    const int b = blockIdx.x, t = threadIdx.x;
    const int c0 = 2 * t, c1 = 2 * t + 1;
    const int a = g_cnt[b * NCELL + c0];
    const int d = g_cnt[b * NCELL + c1];
    s[t] = a + d;
    __syncthreads();
    for (int off = 1; off < NCELL / 2; off <<= 1) {
        int v = (t >= off) ? s[t - off] : 0;
        __syncthreads();
        s[t] += v;
        __syncthreads();
    }
    const int incl = s[t];
    g_start[b * (NCELL + 1) + c1]     = incl - d;  // through c0
    g_start[b * (NCELL + 1) + c1 + 1] = incl;      // through c1
    if (t == 0) g_start[b * (NCELL + 1)] = 0;
    g_cnt[b * NCELL + c0] = 0;     // reset for next replay
    g_cnt[b * NCELL + c1] = 0;
}

__global__ __launch_bounds__(256) void knn_scatter(const float* __restrict__ coords) {
    const int t = blockIdx.x * 256 + threadIdx.x;
    const int b = t >> 13, q = t & (NN - 1);
    const int pack = g_pack[t];
    const int c = pack >> 13, rank = pack & 8191;
    const int pos = g_start[b * (NCELL + 1) + c] + rank;
    const float* cp = coords + ((size_t)b * NN + q) * 3;
    const float x = cp[0], y = cp[1], z = cp[2];
    const float csq = fmaf(z, z, fmaf(y, y, x * x));
    g_sorted[(size_t)b * NN + pos] = make_float4(x, y, z, csq);
    g_sidx[(size_t)b * NN + pos] = q;
}

// ---------------------------------------------------------------------------
// Exact KNN: 8 threads per query (candidate slices mod 8), expanding
// Chebyshev rings over sorted points. Row-level lower-bound skipping vs
// ub16 (= max over slices of slice-2nd-smallest: a provable upper bound on
// the merged 16th). Mid-ring termination for R>=2 with bound (R-1)*CS.
// Top-16 per slice kept UNSORTED via replace-max with exact tie handling.
// Sort + 3-stage bitonic merge at the end. Keys = (sortable(d)<<32)|idx.
// ---------------------------------------------------------------------------
__device__ __forceinline__ u64 u64min(u64 a, u64 b) { return a < b ? a : b; }
__device__ __forceinline__ u64 u64max(u64 a, u64 b) { return a < b ? b : a; }
__device__ __forceinline__ float key_to_dist(u64 k) {
    const unsigned hs = (unsigned)(k >> 32);
    const unsigned ob = (hs & 0x80000000u) ? (hs ^ 0x80000000u) : ~hs;
    return __uint_as_float(ob);
}
__device__ __forceinline__ void insert_key(u64 (&keys)[KK], u64& mx, const u64 k_) {
#pragma unroll
    for (int j = 0; j < KK; j++) keys[j] = (keys[j] == mx) ? k_ : keys[j];
    u64 a0 = u64max(keys[0], keys[1]);
    u64 a1 = u64max(keys[2], keys[3]);
    u64 a2 = u64max(keys[4], keys[5]);
    u64 a3 = u64max(keys[6], keys[7]);
    u64 a4 = u64max(keys[8], keys[9]);
    u64 a5 = u64max(keys[10], keys[11]);
    u64 a6 = u64max(keys[12], keys[13]);
    u64 a7 = u64max(keys[14], keys[15]);
    a0 = u64max(a0, a1); a2 = u64max(a2, a3);
    a4 = u64max(a4, a5); a6 = u64max(a6, a7);
    a0 = u64max(a0, a2); a4 = u64max(a4, a6);
    mx = u64max(a0, a4);
}

__global__ __launch_bounds__(128, 6) void knn_main() {
    const int tt = blockIdx.x * 128 + threadIdx.x;
    const int pt = tt >> 3;           // query point
    const int parity = tt & 7;        // candidate slice
    const int lane = threadIdx.x & 31;
    const unsigned gmask = 0xFFu << (lane & 24);  // the 8 threads of this query
    const int b = pt >> 13, slot = pt & (NN - 1);
    const float4* sp = g_sorted + (size_t)b * NN;
    const int* sidx = g_sidx + (size_t)b * NN;
    const float4 me = sp[slot];
    const float qx = me.x, qy = me.y, qz = me.z;
    const float qsq = me.w;
    const int cx = min(GRID - 1, max(0, (int)(qx * (float)GRID)));
    const int cy = min(GRID - 1, max(0, (int)(qy * (float)GRID)));
    const int cz = min(GRID - 1, max(0, (int)(qz * (float)GRID)));

    u64 keys[KK];
#pragma unroll
    for (int j = 0; j < KK; j++) keys[j] = 0xFF80000000000000ull | (unsigned)j;  // distinct sentinels
    u64 mx = 0xFF80000000000000ull | (unsigned)(KK - 1);
    float thr  = __int_as_float(0x7F800000);  // slice 16th distance (sq)
    float ub16 = __int_as_float(0x7F800000);  // group upper bound on merged 16th (sq)
    float gate = __int_as_float(0x7F800000);  // min(thr, ub16)
    float mn1  = __int_as_float(0x7F800000);  // slice smallest (sq)
    float mn2  = __int_as_float(0x7F800000);  // slice 2nd smallest (sq)

    const int* st = g_start + b * (NCELL + 1);

#define SCAN_RANGE(PA, PB)                                                     \
    for (int p = (PA) + ((parity - (PA)) & 7); p < (PB); p += 8) {             \
        const float4 cd = sp[p];                                               \
        const float dot = fmaf(qz, cd.z, fmaf(qy, cd.y, qx * cd.x));           \
        const float d = fmaf(-2.0f, dot, qsq + cd.w);                          \
        if (d <= gate) {                                                       \
            unsigned s_ = __float_as_uint(d);                                  \
            s_ ^= (unsigned)((int)s_ >> 31) | 0x80000000u;                     \
            const u64 k_ = ((u64)s_ << 32) | (unsigned)sidx[p];                \
            if (k_ < mx) {                                                     \
                insert_key(keys, mx, k_);                                      \
                thr = key_to_dist(mx);                                         \
                gate = fminf(thr, ub16);                                       \
                if (d < mn1) { mn2 = mn1; mn1 = d; }                           \
                else if (d < mn2) { mn2 = d; }                                 \
            }                                                                  \
        }                                                                      \
    }

#define REFRESH_UB()                                                           \
    {                                                                          \
        float m2v = mn2;                                                       \
        m2v = fmaxf(m2v, __shfl_xor_sync(gmask, m2v, 1));                      \
        m2v = fmaxf(m2v, __shfl_xor_sync(gmask, m2v, 2));                      \
        m2v = fmaxf(m2v, __shfl_xor_sync(gmask, m2v, 4));                      \
        ub16 = m2v;                                                            \
        gate = fminf(thr, ub16);                                               \
    }

#define COUNT_BELOW(BK, CNT)                                                   \
    {                                                                          \
        int c_ = 0;                                                            \
        _Pragma("unroll")                                                      \
        for (int j = 0; j < KK; j++) c_ += (keys[j] < (BK)) ? 1 : 0;           \
        c_ += __shfl_xor_sync(gmask, c_, 1);                                   \
        c_ += __shfl_xor_sync(gmask, c_, 2);                                   \
        c_ += __shfl_xor_sync(gmask, c_, 4);                                   \
        (CNT) = c_;                                                            \
    }

    bool done = false;
    for (int R = 0; R <= GRID - 1 && !done; ++R) {
        const int z0 = max(cz - R, 0), z1 = min(cz + R, GRID - 1);
        const int y0 = max(cy - R, 0), y1 = min(cy + R, GRID - 1);
        const int x0 = max(cx - R, 0), x1 = min(cx + R, GRID - 1);
        // mid-ring termination key (valid for R>=2): unscanned >= (R-1)*CS
        u64 midbk = 0;
        if (R >= 2) {
            const float mb = (float)(R - 1) * CS;
            const float mbd = mb * mb * 0.9999f;
            unsigned sb = __float_as_uint(mbd);
            sb ^= (unsigned)((int)sb >> 31) | 0x80000000u;
            midbk = (u64)sb << 32;
        }
        for (int z = z0; z <= z1 && !done; z++) {
            const int az = z - cz;
            const float fz = (az < 0) ? (qz - (float)(z + 1) * CS)
                                      : ((az > 0) ? ((float)z * CS - qz) : 0.f);
            const float fz2 = fz * fz;
            for (int y = y0; y <= y1 && !done; y++) {
                const int ay = y - cy;
                const float fy = (ay < 0) ? (qy - (float)(y + 1) * CS)
                                          : ((ay > 0) ? ((float)y * CS - qy) : 0.f);
                const float ryz = fmaf(fy, fy, fz2);
                const int m2 = max(abs(az), abs(ay));
                const int rowbase = (z * GRID + y) * GRID;
                bool scanned = false;
                if (m2 == R) {
                    // whole row on the ring (x-range spans cx => fx = 0)
                    if (ryz <= ub16) {
                        const int pa = st[rowbase + x0];
                        const int pb = st[rowbase + x1 + 1];
                        SCAN_RANGE(pa, pb)
                        scanned = true;
                    }
                } else {
                    const int xl = cx - R, xr = cx + R;
                    if (xl >= 0) {
                        const float fx = qx - (float)(xl + 1) * CS;
                        if (fmaf(fx, fx, ryz) <= ub16) {
                            const int pa = st[rowbase + xl];
                            const int pb = st[rowbase + xl + 1];
                            SCAN_RANGE(pa, pb)
                            scanned = true;
                        }
                    }
                    if (xr <= GRID - 1) {
                        const float fx = (float)xr * CS - qx;
                        if (fmaf(fx, fx, ryz) <= ub16) {
                            const int pa = st[rowbase + xr];
                            const int pb = st[rowbase + xr + 1];
                            SCAN_RANGE(pa, pb)
                            scanned = true;
                        }
                    }
                }
                if (scanned) {        // group-uniform condition
                    REFRESH_UB()
                    if (R >= 2) {
                        int cnt;
                        COUNT_BELOW(midbk, cnt)
                        if (cnt >= KK) done = true;
                    }
                }
            }
        }
        if (!done) {
            // full-ring termination: unscanned cells >= R*CS away
            const float bound = (float)R * CS;
            const float bd = bound * bound * 0.9999f;
            unsigned sb = __float_as_uint(bd);
            sb ^= (unsigned)((int)sb >> 31) | 0x80000000u;
            const u64 bk = (u64)sb << 32;
            int cnt;
            COUNT_BELOW(bk, cnt)
            if (cnt >= KK) done = true;
        }
    }
#undef SCAN_RANGE
#undef REFRESH_UB
#undef COUNT_BELOW

    // per-thread bitonic sort of the 16 keys (ascending)
#pragma unroll
    for (int kk2 = 2; kk2 <= KK; kk2 <<= 1) {
#pragma unroll
        for (int j = kk2 >> 1; j > 0; j >>= 1) {
#pragma unroll
            for (int i = 0; i < KK; i++) {
                if ((i & j) == 0) {
                    const int l = i | j;
                    const bool up = ((i & kk2) == 0);
                    const u64 lo = u64min(keys[i], keys[l]);
                    const u64 hi = u64max(keys[i], keys[l]);
                    keys[i] = up ? lo : hi;
                    keys[l] = up ? hi : lo;
                }
            }
        }
    }

    // exact merge: three bitonic stages (partners xor 1, xor 2, xor 4)
#pragma unroll
    for (int stage = 0; stage < 3; stage++) {
        const int px = 1 << stage;
        u64 m[KK];
#pragma unroll
        for (int i = 0; i < KK; i++) {
            const u64 pk = __shfl_xor_sync(gmask, keys[KK - 1 - i], px);
            m[i] = u64min(keys[i], pk);   // 16 smallest of union, bitonic order
        }
#pragma unroll
        for (int s = 8; s >= 1; s >>= 1) {
#pragma unroll
            for (int i = 0; i < KK; i++) {
                if ((i & s) == 0) {
                    const u64 lo = u64min(m[i], m[i + s]);
                    const u64 hi = u64max(m[i], m[i + s]);
                    m[i] = lo; m[i + s] = hi;
                }
            }
        }
#pragma unroll
        for (int i = 0; i < KK; i++) keys[i] = m[i];
    }
    if (parity == 0) {
        const int q = sidx[slot];
        int* outp = g_knn + ((size_t)b * NN + q) * KK;
#pragma unroll
        for (int j = 0; j < KK; j++) outp[j] = (int)(keys[j] & 0xFFFFFFFFu);
    }
}

// ---------------------------------------------------------------------------
// Fused gather + collapsed-affine evaluation:
//   out_sum = W*s1 + C1,  pool = max_k g_k[:64],  aggr = W*s2 + C2
// One warp per point; sums accumulate in registers during the gather.
// ---------------------------------------------------------------------------
__device__ __forceinline__ void F2(u64& d, u64 a, u64 b) {
    asm("fma.rn.f32x2 %0, %1, %2, %0;" : "+l"(d) : "l"(a), "l"(b));
}
__device__ __forceinline__ float HADD(u64 v) {
    return __uint_as_float((unsigned)v) + __uint_as_float((unsigned)(v >> 32));
}
#define LD4(p)  (*reinterpret_cast<const float4*>(p))
#define LDU2(p) (*reinterpret_cast<const ulonglong2*>(p))

__global__ __launch_bounds__(256) void mlp2_kernel(
    const float* __restrict__ pf, const float* __restrict__ coords,
    const float* __restrict__ aggr_w, float* __restrict__ out)
{
    __shared__ __align__(16) float s_W[COUT * 68];
    __shared__ float s_C1[COUT], s_C2[COUT], s_u[KK];
    __shared__ __align__(16) float s_s[8][2][68];

    const int tid  = threadIdx.x;
    const int lane = tid & 31;
    const int w    = tid >> 5;

    for (int i = tid; i < COUT * 68; i += 256) s_W[i] = g_W[i];
    if (tid < 64) s_C1[tid] = g_C1[tid];
    else if (tid < 128) s_C2[tid - 64] = g_C2[tid - 64];
    else if (tid < 144) s_u[tid - 128] = aggr_w[tid - 128];
    __syncthreads();

    const int gp = blockIdx.x * 8 + w;
    const int b  = gp >> 13;
    const float* pfb = pf + (size_t)b * NN * CIN;
    const float* cob = coords + (size_t)b * NN * 3;

    const int nk = g_knn[(size_t)gp * KK + (lane & 15)];
    const int cc = (lane & 15) * 4;

    float4 pool = make_float4(-3.4e38f, -3.4e38f, -3.4e38f, -3.4e38f);
    float4 a1 = make_float4(0.f, 0.f, 0.f, 0.f);
    float4 a2 = a1;
#pragma unroll
    for (int k2 = 0; k2 < KK; k2 += 2) {
        const int k = k2 + (lane >> 4);
        const int m = __shfl_sync(0xffffffffu, nk, k);
        const float u = s_u[k];
        const float4 v = LD4(pfb + (size_t)m * CIN + cc);
        pool.x = fmaxf(pool.x, v.x); pool.y = fmaxf(pool.y, v.y);
        pool.z = fmaxf(pool.z, v.z); pool.w = fmaxf(pool.w, v.w);
        a1.x += v.x; a1.y += v.y; a1.z += v.z; a1.w += v.w;
        a2.x = fmaf(u, v.x, a2.x); a2.y = fmaf(u, v.y, a2.y);
        a2.z = fmaf(u, v.z, a2.z); a2.w = fmaf(u, v.w, a2.w);
    }
    // combine the two k-halves (lane <-> lane+16)
    pool.x = fmaxf(pool.x, __shfl_xor_sync(0xffffffffu, pool.x, 16));
    pool.y = fmaxf(pool.y, __shfl_xor_sync(0xffffffffu, pool.y, 16));
    pool.z = fmaxf(pool.z, __shfl_xor_sync(0xffffffffu, pool.z, 16));
    pool.w = fmaxf(pool.w, __shfl_xor_sync(0xffffffffu, pool.w, 16));
    a1.x += __shfl_xor_sync(0xffffffffu, a1.x, 16);
    a1.y += __shfl_xor_sync(0xffffffffu, a1.y, 16);
    a1.z += __shfl_xor_sync(0xffffffffu, a1.z, 16);
    a1.w += __shfl_xor_sync(0xffffffffu, a1.w, 16);
    a2.x += __shfl_xor_sync(0xffffffffu, a2.x, 16);
    a2.y += __shfl_xor_sync(0xffffffffu, a2.y, 16);
    a2.z += __shfl_xor_sync(0xffffffffu, a2.z, 16);
    a2.w += __shfl_xor_sync(0xffffffffu, a2.w, 16);

    // relative-coord channel sums (channels 64..66)
    const int m0 = __shfl_sync(0xffffffffu, nk, 0);
    const float c0x = cob[(size_t)m0 * 3 + 0];
    const float c0y = cob[(size_t)m0 * 3 + 1];
    const float c0z = cob[(size_t)m0 * 3 + 2];
    float dx = 0.f, dy = 0.f, dz = 0.f, ex = 0.f, ey = 0.f, ez = 0.f;
    if (lane < KK) {
        const float* cp = cob + (size_t)nk * 3;
        dx = cp[0] - c0x; dy = cp[1] - c0y; dz = cp[2] - c0z;
        const float u = s_u[lane];
        ex = u * dx; ey = u * dy; ez = u * dz;
    }
#pragma unroll
    for (int s = 8; s >= 1; s >>= 1) {
        dx += __shfl_xor_sync(0xffffffffu, dx, s);
        dy += __shfl_xor_sync(0xffffffffu, dy, s);
        dz += __shfl_xor_sync(0xffffffffu, dz, s);
        ex += __shfl_xor_sync(0xffffffffu, ex, s);
        ey += __shfl_xor_sync(0xffffffffu, ey, s);
        ez += __shfl_xor_sync(0xffffffffu, ez, s);
    }

    if (lane < 16) {
        *reinterpret_cast<float4*>(&s_s[w][0][cc]) = a1;
        *reinterpret_cast<float4*>(&s_s[w][1][cc]) = a2;
    }
    if (lane == 0) {
        s_s[w][0][64] = dx; s_s[w][0][65] = dy; s_s[w][0][66] = dz; s_s[w][0][67] = 0.f;
        s_s[w][1][64] = ex; s_s[w][1][65] = ey; s_s[w][1][66] = ez; s_s[w][1][67] = 0.f;
    }
    __syncwarp();

    // two 64x67 matvecs: lane handles outputs (lane, lane+32) for s1 and s2
    u64 A1 = 0, B1 = 0, A2 = 0, B2 = 0;
#pragma unroll
    for (int c = 0; c < 68; c += 4) {
        const ulonglong2 wA = LDU2(s_W + lane * 68 + c);
        const ulonglong2 wB = LDU2(s_W + (lane + 32) * 68 + c);
        const ulonglong2 x1 = LDU2(&s_s[w][0][c]);
        const ulonglong2 x2 = LDU2(&s_s[w][1][c]);
        F2(A1, x1.x, wA.x); F2(A1, x1.y, wA.y);
        F2(B1, x1.x, wB.x); F2(B1, x1.y, wB.y);
        F2(A2, x2.x, wA.x); F2(A2, x2.y, wA.y);
        F2(B2, x2.x, wB.x); F2(B2, x2.y, wB.y);
    }

    float* op = out + (size_t)gp * 192;
    op[lane]        = HADD(A1) + s_C1[lane];
    op[32 + lane]   = HADD(B1) + s_C1[lane + 32];
    op[128 + lane]  = HADD(A2) + s_C2[lane];
    op[160 + lane]  = HADD(B2) + s_C2[lane + 32];
    if (lane < 16) *reinterpret_cast<float4*>(op + 64 + cc) = pool;
}

// ---------------------------------------------------------------------------
extern "C" void kernel_launch(void* const* d_in, const int* in_sizes, int n_in,
                              void* d_out, int out_size) {
    const float* pf     = (const float*)d_in[0];
    const float* coords = (const float*)d_in[1];
    const float* w1     = (const float*)d_in[2];
    const float* b1     = (const float*)d_in[3];
    const float* w2     = (const float*)d_in[4];
    const float* b2     = (const float*)d_in[5];
    const float* w3     = (const float*)d_in[6];
    const float* b3     = (const float*)d_in[7];
    const float* aw     = (const float*)d_in[8];
    const float* ab     = (const float*)d_in[9];
    float* out = (float*)d_out;

    knn_bin_pre<<<65, 256>>>(coords, w1, b1, w2, b2, w3, b3, aw, ab);
    knn_scan<<<BB, NCELL / 2>>>();
    knn_scatter<<<BB * NN / 256, 256>>>(coords);
    knn_main<<<BB * NN * SLC / 128, 128>>>();
    mlp2_kernel<<<(BB * NN) / 8, 256>>>(pf, coords, aw, out);
}

// round 14
// speedup vs baseline: 1.0346x; 1.0346x over previous
#include <cuda_runtime.h>
#include <cstdint>

#define BB   2
#define NN   8192
#define CIN  64
#define CCAT 67
#define KK   16
#define H1   32
#define H2   64
#define COUT 64

#define GRID 12           // 12x12x12 cells (~4.7 pts/cell)
#define NCELL (GRID*GRID*GRID)
#define CS   (1.0f/12.0f) // cell size

#define SLC  4            // candidate slices per query

typedef unsigned long long u64;

__device__ int    g_knn[BB * NN * KK];
__device__ int    g_cnt[BB * NCELL];          // zero-initialized; scan resets it
__device__ int    g_pack[BB * NN];            // (cell<<13)|rank from bin
__device__ int    g_start[BB * (NCELL + 1)];
__device__ float4 g_sorted[BB * NN];          // (x, y, z, |c|^2)
__device__ int    g_sidx[BB * NN];            // original point index
__device__ float  g_W[COUT * 68];             // collapsed MLP matrix, col 67 = 0
__device__ float  g_C1[COUT];                 // 16 * B
__device__ float  g_C2[COUT];                 // sum(aggr_w) * B + aggr_b

__device__ __forceinline__ int cell_of(float x, float y, float z) {
    int ix = min(GRID - 1, max(0, (int)(x * (float)GRID)));
    int iy = min(GRID - 1, max(0, (int)(y * (float)GRID)));
    int iz = min(GRID - 1, max(0, (int)(z * (float)GRID)));
    return (iz * GRID + iy) * GRID + ix;
}

// ---------------------------------------------------------------------------
// Collapse the affine MLP:  W = w3*w2*w1,  B = w3*(w2*b1 + b2) + b3
// ---------------------------------------------------------------------------
__device__ void precomp_body(
    const float* __restrict__ w1, const float* __restrict__ b1,
    const float* __restrict__ w2, const float* __restrict__ b2,
    const float* __restrict__ w3, const float* __restrict__ b3,
    const float* __restrict__ aggr_w, const float* __restrict__ aggr_b)
{
    __shared__ float s0[4192];       // w1(2144)+w2(2048); later reused for w3(4096)
    __shared__ float s21[64 * 67];   // w2*w1
    __shared__ float st[64];         // w2*b1 + b2
    __shared__ float s_sumU;
    float* sw1 = s0;
    float* sw2 = s0 + 2144;
    const int t = threadIdx.x;
    for (int i = t; i < 2144; i += 256) sw1[i] = w1[i];
    for (int i = t; i < 2048; i += 256) sw2[i] = w2[i];
    if (t == 0) {
        float s = 0.f;
        for (int k = 0; k < KK; k++) s += aggr_w[k];
        s_sumU = s;
    }
    __syncthreads();
    if (t < 64) {
        float acc = b2[t];
        for (int j = 0; j < 32; j++) acc = fmaf(sw2[t * 32 + j], b1[j], acc);
        st[t] = acc;
    }
    for (int i = t; i < 64 * 67; i += 256) {
        int o = i / 67, c = i % 67;
        float acc = 0.f;
        for (int j = 0; j < 32; j++) acc = fmaf(sw2[o * 32 + j], sw1[j * 67 + c], acc);
        s21[i] = acc;
    }
    __syncthreads();
    float* sw3 = s0;                 // overlay (w1/w2 dead)
    for (int i = t; i < 4096; i += 256) sw3[i] = w3[i];
    __syncthreads();
    for (int i = t; i < 64 * 68; i += 256) {
        int o = i / 68, c = i % 68;
        float acc = 0.f;
        if (c < 67)
            for (int j = 0; j < 64; j++) acc = fmaf(sw3[o * 64 + j], s21[j * 67 + c], acc);
        g_W[i] = acc;                // col 67 stays 0 (pad)
    }
    if (t < 64) {
        float B = b3[t];
        for (int j = 0; j < 64; j++) B = fmaf(sw3[t * 64 + j], st[j], B);
        g_C1[t] = 16.0f * B;
        g_C2[t] = fmaf(s_sumU, B, aggr_b[0]);
    }
}

// bin (blocks 0..63) + precomp (block 64)
__global__ __launch_bounds__(256) void knn_bin_pre(
    const float* __restrict__ coords,
    const float* __restrict__ w1, const float* __restrict__ b1,
    const float* __restrict__ w2, const float* __restrict__ b2,
    const float* __restrict__ w3, const float* __restrict__ b3,
    const float* __restrict__ aggr_w, const float* __restrict__ aggr_b)
{
    if (blockIdx.x == 64) {
        precomp_body(w1, b1, w2, b2, w3, b3, aggr_w, aggr_b);
        return;
    }
    const int t = blockIdx.x * 256 + threadIdx.x;
    const int b = t >> 13, q = t & (NN - 1);
    const float* cp = coords + ((size_t)b * NN + q) * 3;
    const int c = cell_of(cp[0], cp[1], cp[2]);
    const int rank = atomicAdd(&g_cnt[b * NCELL + c], 1);
    g_pack[t] = (c << 13) | rank;
}

// prefix-sum over 1728 cells: 864 threads x 2 cells each
__global__ __launch_bounds__(NCELL / 2) void knn_scan() {
    __shared__ int s[NCELL / 2];
    const int b = blockIdx.x, t = threadIdx.x;
    const int c0 = 2 * t, c1 = 2 * t + 1;
    const int a = g_cnt[b * NCELL + c0];
    const int d = g_cnt[b * NCELL + c1];
    s[t] = a + d;
    __syncthreads();
    for (int off = 1; off < NCELL / 2; off <<= 1) {
        int v = (t >= off) ? s[t - off] : 0;
        __syncthreads();
        s[t] += v;
        __syncthreads();
    }
    const int incl = s[t];
    g_start[b * (NCELL + 1) + c1]     = incl - d;  // through c0
    g_start[b * (NCELL + 1) + c1 + 1] = incl;      // through c1
    if (t == 0) g_start[b * (NCELL + 1)] = 0;
    g_cnt[b * NCELL + c0] = 0;     // reset for next replay
    g_cnt[b * NCELL + c1] = 0;
}

__global__ __launch_bounds__(256) void knn_scatter(const float* __restrict__ coords) {
    const int t = blockIdx.x * 256 + threadIdx.x;
    const int b = t >> 13, q = t & (NN - 1);
    const int pack = g_pack[t];
    const int c = pack >> 13, rank = pack & 8191;
    const int pos = g_start[b * (NCELL + 1) + c] + rank;
    const float* cp = coords + ((size_t)b * NN + q) * 3;
    const float x = cp[0], y = cp[1], z = cp[2];
    const float csq = fmaf(z, z, fmaf(y, y, x * x));
    g_sorted[(size_t)b * NN + pos] = make_float4(x, y, z, csq);
    g_sidx[(size_t)b * NN + pos] = q;
}

// ---------------------------------------------------------------------------
// Exact KNN: 4 threads per query (candidate slices mod 4), expanding
// Chebyshev rings over sorted points. Row-level lower-bound skipping vs
// ub16 = min( max_j(slice 4th-smallest), min_j(slice 16th) ) — both are
// provable upper bounds on the merged 16th (4x4=16 distinct elements below
// the max; the min-thr slice alone holds 16 below its thr). Mid-ring
// termination for R>=2 with bound (R-1)*CS. Top-16 per slice UNSORTED via
// replace-max with exact tie handling; sort + 2-stage bitonic merge at the
// end. Keys = (sortable(d)<<32)|idx = stable (d, idx) order (top_k ties).
// ---------------------------------------------------------------------------
__device__ __forceinline__ u64 u64min(u64 a, u64 b) { return a < b ? a : b; }
__device__ __forceinline__ u64 u64max(u64 a, u64 b) { return a < b ? b : a; }
__device__ __forceinline__ float key_to_dist(u64 k) {
    const unsigned hs = (unsigned)(k >> 32);
    const unsigned ob = (hs & 0x80000000u) ? (hs ^ 0x80000000u) : ~hs;
    return __uint_as_float(ob);
}
__device__ __forceinline__ void insert_key(u64 (&keys)[KK], u64& mx, const u64 k_) {
#pragma unroll
    for (int j = 0; j < KK; j++) keys[j] = (keys[j] == mx) ? k_ : keys[j];
    u64 a0 = u64max(keys[0], keys[1]);
    u64 a1 = u64max(keys[2], keys[3]);
    u64 a2 = u64max(keys[4], keys[5]);
    u64 a3 = u64max(keys[6], keys[7]);
    u64 a4 = u64max(keys[8], keys[9]);
    u64 a5 = u64max(keys[10], keys[11]);
    u64 a6 = u64max(keys[12], keys[13]);
    u64 a7 = u64max(keys[14], keys[15]);
    a0 = u64max(a0, a1); a2 = u64max(a2, a3);
    a4 = u64max(a4, a5); a6 = u64max(a6, a7);
    a0 = u64max(a0, a2); a4 = u64max(a4, a6);
    mx = u64max(a0, a4);
}

__global__ __launch_bounds__(128, 6) void knn_main() {
    const int tt = blockIdx.x * 128 + threadIdx.x;
    const int pt = tt >> 2;           // query point
    const int parity = tt & 3;        // candidate slice
    const int lane = threadIdx.x & 31;
    const unsigned gmask = 0xFu << (lane & 28);  // the 4 threads of this query
    const int b = pt >> 13, slot = pt & (NN - 1);
    const float4* sp = g_sorted + (size_t)b * NN;
    const int* sidx = g_sidx + (size_t)b * NN;
    const float4 me = sp[slot];
    const float qx = me.x, qy = me.y, qz = me.z;
    const float qsq = me.w;
    const int cx = min(GRID - 1, max(0, (int)(qx * (float)GRID)));
    const int cy = min(GRID - 1, max(0, (int)(qy * (float)GRID)));
    const int cz = min(GRID - 1, max(0, (int)(qz * (float)GRID)));

    u64 keys[KK];
#pragma unroll
    for (int j = 0; j < KK; j++) keys[j] = 0xFF80000000000000ull | (unsigned)j;  // distinct sentinels
    u64 mx = 0xFF80000000000000ull | (unsigned)(KK - 1);
    float thr  = __int_as_float(0x7F800000);  // slice 16th distance (sq)
    float ub16 = __int_as_float(0x7F800000);  // group upper bound on merged 16th (sq)
    float gate = __int_as_float(0x7F800000);  // min(thr, ub16)
    float mn[4];                              // slice 4 smallest (sq), ascending
    mn[0] = mn[1] = mn[2] = mn[3] = __int_as_float(0x7F800000);

    const int* st = g_start + b * (NCELL + 1);

#define SCAN_RANGE(PA, PB)                                                     \
    for (int p = (PA) + ((parity - (PA)) & 3); p < (PB); p += 4) {             \
        const float4 cd = sp[p];                                               \
        const float dot = fmaf(qz, cd.z, fmaf(qy, cd.y, qx * cd.x));           \
        const float d = fmaf(-2.0f, dot, qsq + cd.w);                          \
        if (d <= gate) {                                                       \
            unsigned s_ = __float_as_uint(d);                                  \
            s_ ^= (unsigned)((int)s_ >> 31) | 0x80000000u;                     \
            const u64 k_ = ((u64)s_ << 32) | (unsigned)sidx[p];                \
            if (k_ < mx) {                                                     \
                insert_key(keys, mx, k_);                                      \
                thr = key_to_dist(mx);                                         \
                gate = fminf(thr, ub16);                                       \
                float t_ = d;                                                  \
                _Pragma("unroll")                                              \
                for (int j = 0; j < 4; j++) {                                  \
                    const float mj = mn[j];                                    \
                    const bool cl = t_ < mj;                                   \
                    mn[j] = cl ? t_ : mj;                                      \
                    t_ = cl ? mj : t_;                                         \
                }                                                              \
            }                                                                  \
        }                                                                      \
    }

#define REFRESH_UB()                                                           \
    {                                                                          \
        float m4v = mn[3];                                                     \
        m4v = fmaxf(m4v, __shfl_xor_sync(gmask, m4v, 1));                      \
        m4v = fmaxf(m4v, __shfl_xor_sync(gmask, m4v, 2));                      \
        float tmn = thr;                                                       \
        tmn = fminf(tmn, __shfl_xor_sync(gmask, tmn, 1));                      \
        tmn = fminf(tmn, __shfl_xor_sync(gmask, tmn, 2));                      \
        ub16 = fminf(m4v, tmn);                                                \
        gate = fminf(thr, ub16);                                               \
    }

#define COUNT_BELOW(BK, CNT)                                                   \
    {                                                                          \
        int c_ = 0;                                                            \
        _Pragma("unroll")                                                      \
        for (int j = 0; j < KK; j++) c_ += (keys[j] < (BK)) ? 1 : 0;           \
        c_ += __shfl_xor_sync(gmask, c_, 1);                                   \
        c_ += __shfl_xor_sync(gmask, c_, 2);                                   \
        (CNT) = c_;                                                            \
    }

    bool done = false;
    for (int R = 0; R <= GRID - 1 && !done; ++R) {
        const int z0 = max(cz - R, 0), z1 = min(cz + R, GRID - 1);
        const int y0 = max(cy - R, 0), y1 = min(cy + R, GRID - 1);
        const int x0 = max(cx - R, 0), x1 = min(cx + R, GRID - 1);
        // mid-ring termination key (valid for R>=2): unscanned >= (R-1)*CS
        u64 midbk = 0;
        if (R >= 2) {
            const float mb = (float)(R - 1) * CS;
            const float mbd = mb * mb * 0.9999f;
            unsigned sb = __float_as_uint(mbd);
            sb ^= (unsigned)((int)sb >> 31) | 0x80000000u;
            midbk = (u64)sb << 32;
        }
        for (int z = z0; z <= z1 && !done; z++) {
            const int az = z - cz;
            const float fz = (az < 0) ? (qz - (float)(z + 1) * CS)
                                      : ((az > 0) ? ((float)z * CS - qz) : 0.f);
            const float fz2 = fz * fz;
            for (int y = y0; y <= y1 && !done; y++) {
                const int ay = y - cy;
                const float fy = (ay < 0) ? (qy - (float)(y + 1) * CS)
                                          : ((ay > 0) ? ((float)y * CS - qy) : 0.f);
                const float ryz = fmaf(fy, fy, fz2);
                const int m2 = max(abs(az), abs(ay));
                const int rowbase = (z * GRID + y) * GRID;
                bool scanned = false;
                if (m2 == R) {
                    // whole row on the ring (x-range spans cx => fx = 0)
                    if (ryz <= ub16) {
                        const int pa = st[rowbase + x0];
                        const int pb = st[rowbase + x1 + 1];
                        SCAN_RANGE(pa, pb)
                        scanned = true;
                    }
                } else {
                    const int xl = cx - R, xr = cx + R;
                    if (xl >= 0) {
                        const float fx = qx - (float)(xl + 1) * CS;
                        if (fmaf(fx, fx, ryz) <= ub16) {
                            const int pa = st[rowbase + xl];
                            const int pb = st[rowbase + xl + 1];
                            SCAN_RANGE(pa, pb)
                            scanned = true;
                        }
                    }
                    if (xr <= GRID - 1) {
                        const float fx = (float)xr * CS - qx;
                        if (fmaf(fx, fx, ryz) <= ub16) {
                            const int pa = st[rowbase + xr];
                            const int pb = st[rowbase + xr + 1];
                            SCAN_RANGE(pa, pb)
                            scanned = true;
                        }
                    }
                }
                if (scanned) {        // group-uniform condition
                    REFRESH_UB()
                    if (R >= 2) {
                        int cnt;
                        COUNT_BELOW(midbk, cnt)
                        if (cnt >= KK) done = true;
                    }
                }
            }
        }
        if (!done) {
            // full-ring termination: unscanned cells >= R*CS away
            const float bound = (float)R * CS;
            const float bd = bound * bound * 0.9999f;
            unsigned sb = __float_as_uint(bd);
            sb ^= (unsigned)((int)sb >> 31) | 0x80000000u;
            const u64 bk = (u64)sb << 32;
            int cnt;
            COUNT_BELOW(bk, cnt)
            if (cnt >= KK) done = true;
        }
    }
#undef SCAN_RANGE
#undef REFRESH_UB
#undef COUNT_BELOW

    // per-thread bitonic sort of the 16 keys (ascending)
#pragma unroll
    for (int kk2 = 2; kk2 <= KK; kk2 <<= 1) {
#pragma unroll
        for (int j = kk2 >> 1; j > 0; j >>= 1) {
#pragma unroll
            for (int i = 0; i < KK; i++) {
                if ((i & j) == 0) {
                    const int l = i | j;
                    const bool up = ((i & kk2) == 0);
                    const u64 lo = u64min(keys[i], keys[l]);
                    const u64 hi = u64max(keys[i], keys[l]);
                    keys[i] = up ? lo : hi;
                    keys[l] = up ? hi : lo;
                }
            }
        }
    }

    // exact merge: two bitonic stages (partners xor 1, xor 2)
#pragma unroll
    for (int stage = 0; stage < 2; stage++) {
        const int px = 1 << stage;
        u64 m[KK];
#pragma unroll
        for (int i = 0; i < KK; i++) {
            const u64 pk = __shfl_xor_sync(gmask, keys[KK - 1 - i], px);
            m[i] = u64min(keys[i], pk);   // 16 smallest of union, bitonic order
        }
#pragma unroll
        for (int s = 8; s >= 1; s >>= 1) {
#pragma unroll
            for (int i = 0; i < KK; i++) {
                if ((i & s) == 0) {
                    const u64 lo = u64min(m[i], m[i + s]);
                    const u64 hi = u64max(m[i], m[i + s]);
                    m[i] = lo; m[i + s] = hi;
                }
            }
        }
#pragma unroll
        for (int i = 0; i < KK; i++) keys[i] = m[i];
    }
    if (parity == 0) {
        const int q = sidx[slot];
        int* outp = g_knn + ((size_t)b * NN + q) * KK;
#pragma unroll
        for (int j = 0; j < KK; j++) outp[j] = (int)(keys[j] & 0xFFFFFFFFu);
    }
}

// ---------------------------------------------------------------------------
// Fused gather + collapsed-affine evaluation:
//   out_sum = W*s1 + C1,  pool = max_k g_k[:64],  aggr = W*s2 + C2
// One warp per point; sums accumulate in registers during the gather.
// ---------------------------------------------------------------------------
__device__ __forceinline__ void F2(u64& d, u64 a, u64 b) {
    asm("fma.rn.f32x2 %0, %1, %2, %0;" : "+l"(d) : "l"(a), "l"(b));
}
__device__ __forceinline__ float HADD(u64 v) {
    return __uint_as_float((unsigned)v) + __uint_as_float((unsigned)(v >> 32));
}
#define LD4(p)  (*reinterpret_cast<const float4*>(p))
#define LDU2(p) (*reinterpret_cast<const ulonglong2*>(p))

__global__ __launch_bounds__(256) void mlp2_kernel(
    const float* __restrict__ pf, const float* __restrict__ coords,
    const float* __restrict__ aggr_w, float* __restrict__ out)
{
    __shared__ __align__(16) float s_W[COUT * 68];
    __shared__ float s_C1[COUT], s_C2[COUT], s_u[KK];
    __shared__ __align__(16) float s_s[8][2][68];

    const int tid  = threadIdx.x;
    const int lane = tid & 31;
    const int w    = tid >> 5;

    for (int i = tid; i < COUT * 68; i += 256) s_W[i] = g_W[i];
    if (tid < 64) s_C1[tid] = g_C1[tid];
    else if (tid < 128) s_C2[tid - 64] = g_C2[tid - 64];
    else if (tid < 144) s_u[tid - 128] = aggr_w[tid - 128];
    __syncthreads();

    const int gp = blockIdx.x * 8 + w;
    const int b  = gp >> 13;
    const float* pfb = pf + (size_t)b * NN * CIN;
    const float* cob = coords + (size_t)b * NN * 3;

    const int nk = g_knn[(size_t)gp * KK + (lane & 15)];
    const int cc = (lane & 15) * 4;

    float4 pool = make_float4(-3.4e38f, -3.4e38f, -3.4e38f, -3.4e38f);
    float4 a1 = make_float4(0.f, 0.f, 0.f, 0.f);
    float4 a2 = a1;
#pragma unroll
    for (int k2 = 0; k2 < KK; k2 += 2) {
        const int k = k2 + (lane >> 4);
        const int m = __shfl_sync(0xffffffffu, nk, k);
        const float u = s_u[k];
        const float4 v = LD4(pfb + (size_t)m * CIN + cc);
        pool.x = fmaxf(pool.x, v.x); pool.y = fmaxf(pool.y, v.y);
        pool.z = fmaxf(pool.z, v.z); pool.w = fmaxf(pool.w, v.w);
        a1.x += v.x; a1.y += v.y; a1.z += v.z; a1.w += v.w;
        a2.x = fmaf(u, v.x, a2.x); a2.y = fmaf(u, v.y, a2.y);
        a2.z = fmaf(u, v.z, a2.z); a2.w = fmaf(u, v.w, a2.w);
    }
    // combine the two k-halves (lane <-> lane+16)
    pool.x = fmaxf(pool.x, __shfl_xor_sync(0xffffffffu, pool.x, 16));
    pool.y = fmaxf(pool.y, __shfl_xor_sync(0xffffffffu, pool.y, 16));
    pool.z = fmaxf(pool.z, __shfl_xor_sync(0xffffffffu, pool.z, 16));
    pool.w = fmaxf(pool.w, __shfl_xor_sync(0xffffffffu, pool.w, 16));
    a1.x += __shfl_xor_sync(0xffffffffu, a1.x, 16);
    a1.y += __shfl_xor_sync(0xffffffffu, a1.y, 16);
    a1.z += __shfl_xor_sync(0xffffffffu, a1.z, 16);
    a1.w += __shfl_xor_sync(0xffffffffu, a1.w, 16);
    a2.x += __shfl_xor_sync(0xffffffffu, a2.x, 16);
    a2.y += __shfl_xor_sync(0xffffffffu, a2.y, 16);
    a2.z += __shfl_xor_sync(0xffffffffu, a2.z, 16);
    a2.w += __shfl_xor_sync(0xffffffffu, a2.w, 16);

    // relative-coord channel sums (channels 64..66)
    const int m0 = __shfl_sync(0xffffffffu, nk, 0);
    const float c0x = cob[(size_t)m0 * 3 + 0];
    const float c0y = cob[(size_t)m0 * 3 + 1];
    const float c0z = cob[(size_t)m0 * 3 + 2];
    float dx = 0.f, dy = 0.f, dz = 0.f, ex = 0.f, ey = 0.f, ez = 0.f;
    if (lane < KK) {
        const float* cp = cob + (size_t)nk * 3;
        dx = cp[0] - c0x; dy = cp[1] - c0y; dz = cp[2] - c0z;
        const float u = s_u[lane];
        ex = u * dx; ey = u * dy; ez = u * dz;
    }
#pragma unroll
    for (int s = 8; s >= 1; s >>= 1) {
        dx += __shfl_xor_sync(0xffffffffu, dx, s);
        dy += __shfl_xor_sync(0xffffffffu, dy, s);
        dz += __shfl_xor_sync(0xffffffffu, dz, s);
        ex += __shfl_xor_sync(0xffffffffu, ex, s);
        ey += __shfl_xor_sync(0xffffffffu, ey, s);
        ez += __shfl_xor_sync(0xffffffffu, ez, s);
    }

    if (lane < 16) {
        *reinterpret_cast<float4*>(&s_s[w][0][cc]) = a1;
        *reinterpret_cast<float4*>(&s_s[w][1][cc]) = a2;
    }
    if (lane == 0) {
        s_s[w][0][64] = dx; s_s[w][0][65] = dy; s_s[w][0][66] = dz; s_s[w][0][67] = 0.f;
        s_s[w][1][64] = ex; s_s[w][1][65] = ey; s_s[w][1][66] = ez; s_s[w][1][67] = 0.f;
    }
    __syncwarp();

    // two 64x67 matvecs: lane handles outputs (lane, lane+32) for s1 and s2
    u64 A1 = 0, B1 = 0, A2 = 0, B2 = 0;
#pragma unroll
    for (int c = 0; c < 68; c += 4) {
        const ulonglong2 wA = LDU2(s_W + lane * 68 + c);
        const ulonglong2 wB = LDU2(s_W + (lane + 32) * 68 + c);
        const ulonglong2 x1 = LDU2(&s_s[w][0][c]);
        const ulonglong2 x2 = LDU2(&s_s[w][1][c]);
        F2(A1, x1.x, wA.x); F2(A1, x1.y, wA.y);
        F2(B1, x1.x, wB.x); F2(B1, x1.y, wB.y);
        F2(A2, x2.x, wA.x); F2(A2, x2.y, wA.y);
        F2(B2, x2.x, wB.x); F2(B2, x2.y, wB.y);
    }

    float* op = out + (size_t)gp * 192;
    op[lane]        = HADD(A1) + s_C1[lane];
    op[32 + lane]   = HADD(B1) + s_C1[lane + 32];
    op[128 + lane]  = HADD(A2) + s_C2[lane];
    op[160 + lane]  = HADD(B2) + s_C2[lane + 32];
    if (lane < 16) *reinterpret_cast<float4*>(op + 64 + cc) = pool;
}

// ---------------------------------------------------------------------------
extern "C" void kernel_launch(void* const* d_in, const int* in_sizes, int n_in,
                              void* d_out, int out_size) {
    const float* pf     = (const float*)d_in[0];
    const float* coords = (const float*)d_in[1];
    const float* w1     = (const float*)d_in[2];
    const float* b1     = (const float*)d_in[3];
    const float* w2     = (const float*)d_in[4];
    const float* b2     = (const float*)d_in[5];
    const float* w3     = (const float*)d_in[6];
    const float* b3     = (const float*)d_in[7];
    const float* aw     = (const float*)d_in[8];
    const float* ab     = (const float*)d_in[9];
    float* out = (float*)d_out;

    knn_bin_pre<<<65, 256>>>(coords, w1, b1, w2, b2, w3, b3, aw, ab);
    knn_scan<<<BB, NCELL / 2>>>();
    knn_scatter<<<BB * NN / 256, 256>>>(coords);
    knn_main<<<BB * NN * SLC / 128, 128>>>();
    mlp2_kernel<<<(BB * NN) / 8, 256>>>(pf, coords, aw, out);
}

// round 15
// speedup vs baseline: 1.0426x; 1.0077x over previous
#include <cuda_runtime.h>
#include <cstdint>

#define BB   2
#define NN   8192
#define CIN  64
#define CCAT 67
#define KK   16
#define H1   32
#define H2   64
#define COUT 64

#define GRID 12           // 12x12x12 cells (~4.7 pts/cell)
#define NCELL (GRID*GRID*GRID)
#define CS   (1.0f/12.0f) // cell size

#define SLC  4            // candidate slices per query

typedef unsigned long long u64;

__device__ int    g_knn[BB * NN * KK];
__device__ int    g_cnt[BB * NCELL];          // zero-initialized; scan resets it
__device__ int    g_pack[BB * NN];            // (cell<<13)|rank from bin
__device__ int    g_start[BB * (NCELL + 1)];
__device__ float4 g_sorted[BB * NN];          // (x, y, z, |c|^2)
__device__ int    g_sidx[BB * NN];            // original point index
__device__ float  g_W[COUT * 68];             // collapsed MLP matrix, col 67 = 0
__device__ float  g_C1[COUT];                 // 16 * B
__device__ float  g_C2[COUT];                 // sum(aggr_w) * B + aggr_b

__device__ __forceinline__ int cell_of(float x, float y, float z) {
    int ix = min(GRID - 1, max(0, (int)(x * (float)GRID)));
    int iy = min(GRID - 1, max(0, (int)(y * (float)GRID)));
    int iz = min(GRID - 1, max(0, (int)(z * (float)GRID)));
    return (iz * GRID + iy) * GRID + ix;
}

// ---------------------------------------------------------------------------
// Collapse the affine MLP:  W = w3*w2*w1,  B = w3*(w2*b1 + b2) + b3
// ---------------------------------------------------------------------------
__device__ void precomp_body(
    const float* __restrict__ w1, const float* __restrict__ b1,
    const float* __restrict__ w2, const float* __restrict__ b2,
    const float* __restrict__ w3, const float* __restrict__ b3,
    const float* __restrict__ aggr_w, const float* __restrict__ aggr_b)
{
    __shared__ float s0[4192];       // w1(2144)+w2(2048); later reused for w3(4096)
    __shared__ float s21[64 * 67];   // w2*w1
    __shared__ float st[64];         // w2*b1 + b2
    __shared__ float s_sumU;
    float* sw1 = s0;
    float* sw2 = s0 + 2144;
    const int t = threadIdx.x;
    for (int i = t; i < 2144; i += 256) sw1[i] = w1[i];
    for (int i = t; i < 2048; i += 256) sw2[i] = w2[i];
    if (t == 0) {
        float s = 0.f;
        for (int k = 0; k < KK; k++) s += aggr_w[k];
        s_sumU = s;
    }
    __syncthreads();
    if (t < 64) {
        float acc = b2[t];
        for (int j = 0; j < 32; j++) acc = fmaf(sw2[t * 32 + j], b1[j], acc);
        st[t] = acc;
    }
    for (int i = t; i < 64 * 67; i += 256) {
        int o = i / 67, c = i % 67;
        float acc = 0.f;
        for (int j = 0; j < 32; j++) acc = fmaf(sw2[o * 32 + j], sw1[j * 67 + c], acc);
        s21[i] = acc;
    }
    __syncthreads();
    float* sw3 = s0;                 // overlay (w1/w2 dead)
    for (int i = t; i < 4096; i += 256) sw3[i] = w3[i];
    __syncthreads();
    for (int i = t; i < 64 * 68; i += 256) {
        int o = i / 68, c = i % 68;
        float acc = 0.f;
        if (c < 67)
            for (int j = 0; j < 64; j++) acc = fmaf(sw3[o * 64 + j], s21[j * 67 + c], acc);
        g_W[i] = acc;                // col 67 stays 0 (pad)
    }
    if (t < 64) {
        float B = b3[t];
        for (int j = 0; j < 64; j++) B = fmaf(sw3[t * 64 + j], st[j], B);
        g_C1[t] = 16.0f * B;
        g_C2[t] = fmaf(s_sumU, B, aggr_b[0]);
    }
}

// bin (blocks 0..63) + precomp (block 64)
__global__ __launch_bounds__(256) void knn_bin_pre(
    const float* __restrict__ coords,
    const float* __restrict__ w1, const float* __restrict__ b1,
    const float* __restrict__ w2, const float* __restrict__ b2,
    const float* __restrict__ w3, const float* __restrict__ b3,
    const float* __restrict__ aggr_w, const float* __restrict__ aggr_b)
{
    if (blockIdx.x == 64) {
        precomp_body(w1, b1, w2, b2, w3, b3, aggr_w, aggr_b);
        return;
    }
    const int t = blockIdx.x * 256 + threadIdx.x;
    const int b = t >> 13, q = t & (NN - 1);
    const float* cp = coords + ((size_t)b * NN + q) * 3;
    const int c = cell_of(cp[0], cp[1], cp[2]);
    const int rank = atomicAdd(&g_cnt[b * NCELL + c], 1);
    g_pack[t] = (c << 13) | rank;
}

// prefix-sum over 1728 cells: 864 threads x 2 cells each
__global__ __launch_bounds__(NCELL / 2) void knn_scan() {
    __shared__ int s[NCELL / 2];
    const int b = blockIdx.x, t = threadIdx.x;
    const int c0 = 2 * t, c1 = 2 * t + 1;
    const int a = g_cnt[b * NCELL + c0];
    const int d = g_cnt[b * NCELL + c1];
    s[t] = a + d;
    __syncthreads();
    for (int off = 1; off < NCELL / 2; off <<= 1) {
        int v = (t >= off) ? s[t - off] : 0;
        __syncthreads();
        s[t] += v;
        __syncthreads();
    }
    const int incl = s[t];
    g_start[b * (NCELL + 1) + c1]     = incl - d;  // through c0
    g_start[b * (NCELL + 1) + c1 + 1] = incl;      // through c1
    if (t == 0) g_start[b * (NCELL + 1)] = 0;
    g_cnt[b * NCELL + c0] = 0;     // reset for next replay
    g_cnt[b * NCELL + c1] = 0;
}

__global__ __launch_bounds__(256) void knn_scatter(const float* __restrict__ coords) {
    const int t = blockIdx.x * 256 + threadIdx.x;
    const int b = t >> 13, q = t & (NN - 1);
    const int pack = g_pack[t];
    const int c = pack >> 13, rank = pack & 8191;
    const int pos = g_start[b * (NCELL + 1) + c] + rank;
    const float* cp = coords + ((size_t)b * NN + q) * 3;
    const float x = cp[0], y = cp[1], z = cp[2];
    const float csq = fmaf(z, z, fmaf(y, y, x * x));
    g_sorted[(size_t)b * NN + pos] = make_float4(x, y, z, csq);
    g_sidx[(size_t)b * NN + pos] = q;
}

// ---------------------------------------------------------------------------
// Exact KNN: 4 threads per query (candidate slices mod 4), expanding
// Chebyshev rings over sorted points. 2x software-pipelined candidate scan
// (dual LDG.128 in flight). Row-level lower-bound skipping vs ub16 =
// min( max_j(slice 4th-smallest), min_j(slice 16th) ) — both provable upper
// bounds on the merged 16th. Mid-ring termination for R>=2 with (R-1)*CS.
// Top-16 per slice UNSORTED via replace-max (exact tie handling);
// sort + 2-stage bitonic merge at the end. Keys = (sortable(d)<<32)|idx.
// ---------------------------------------------------------------------------
__device__ __forceinline__ u64 u64min(u64 a, u64 b) { return a < b ? a : b; }
__device__ __forceinline__ u64 u64max(u64 a, u64 b) { return a < b ? b : a; }
__device__ __forceinline__ float key_to_dist(u64 k) {
    const unsigned hs = (unsigned)(k >> 32);
    const unsigned ob = (hs & 0x80000000u) ? (hs ^ 0x80000000u) : ~hs;
    return __uint_as_float(ob);
}
__device__ __forceinline__ void insert_key(u64 (&keys)[KK], u64& mx, const u64 k_) {
#pragma unroll
    for (int j = 0; j < KK; j++) keys[j] = (keys[j] == mx) ? k_ : keys[j];
    u64 a0 = u64max(keys[0], keys[1]);
    u64 a1 = u64max(keys[2], keys[3]);
    u64 a2 = u64max(keys[4], keys[5]);
    u64 a3 = u64max(keys[6], keys[7]);
    u64 a4 = u64max(keys[8], keys[9]);
    u64 a5 = u64max(keys[10], keys[11]);
    u64 a6 = u64max(keys[12], keys[13]);
    u64 a7 = u64max(keys[14], keys[15]);
    a0 = u64max(a0, a1); a2 = u64max(a2, a3);
    a4 = u64max(a4, a5); a6 = u64max(a6, a7);
    a0 = u64max(a0, a2); a4 = u64max(a4, a6);
    mx = u64max(a0, a4);
}

__global__ __launch_bounds__(128, 4) void knn_main() {
    const int tt = blockIdx.x * 128 + threadIdx.x;
    const int pt = tt >> 2;           // query point
    const int parity = tt & 3;        // candidate slice
    const int lane = threadIdx.x & 31;
    const unsigned gmask = 0xFu << (lane & 28);  // the 4 threads of this query
    const int b = pt >> 13, slot = pt & (NN - 1);
    const float4* sp = g_sorted + (size_t)b * NN;
    const int* sidx = g_sidx + (size_t)b * NN;
    const float4 me = sp[slot];
    const float qx = me.x, qy = me.y, qz = me.z;
    const float qsq = me.w;
    const int cx = min(GRID - 1, max(0, (int)(qx * (float)GRID)));
    const int cy = min(GRID - 1, max(0, (int)(qy * (float)GRID)));
    const int cz = min(GRID - 1, max(0, (int)(qz * (float)GRID)));

    u64 keys[KK];
#pragma unroll
    for (int j = 0; j < KK; j++) keys[j] = 0xFF80000000000000ull | (unsigned)j;  // distinct sentinels
    u64 mx = 0xFF80000000000000ull | (unsigned)(KK - 1);
    float thr  = __int_as_float(0x7F800000);  // slice 16th distance (sq)
    float ub16 = __int_as_float(0x7F800000);  // group upper bound on merged 16th (sq)
    float gate = __int_as_float(0x7F800000);  // min(thr, ub16)
    float mn[4];                              // slice 4 smallest (sq), ascending
    mn[0] = mn[1] = mn[2] = mn[3] = __int_as_float(0x7F800000);

    const int* st = g_start + b * (NCELL + 1);

#define DO_INSERT(DV, PV)                                                      \
    {                                                                          \
        unsigned s_ = __float_as_uint(DV);                                     \
        s_ ^= (unsigned)((int)s_ >> 31) | 0x80000000u;                         \
        const u64 k_ = ((u64)s_ << 32) | (unsigned)sidx[PV];                   \
        if (k_ < mx) {                                                         \
            insert_key(keys, mx, k_);                                          \
            thr = key_to_dist(mx);                                             \
            gate = fminf(thr, ub16);                                           \
            float t_ = (DV);                                                   \
            _Pragma("unroll")                                                  \
            for (int j = 0; j < 4; j++) {                                      \
                const float mj = mn[j];                                        \
                const bool cl = t_ < mj;                                       \
                mn[j] = cl ? t_ : mj;                                          \
                t_ = cl ? mj : t_;                                             \
            }                                                                  \
        }                                                                      \
    }

#define SCAN_RANGE(PA, PB)                                                     \
    {                                                                          \
        int p = (PA) + ((parity - (PA)) & 3);                                  \
        for (; p + 4 < (PB); p += 8) {                                         \
            const float4 c0 = sp[p];                                           \
            const float4 c1 = sp[p + 4];                                       \
            const float dot0 = fmaf(qz, c0.z, fmaf(qy, c0.y, qx * c0.x));      \
            const float dot1 = fmaf(qz, c1.z, fmaf(qy, c1.y, qx * c1.x));      \
            const float d0 = fmaf(-2.0f, dot0, qsq + c0.w);                    \
            const float d1 = fmaf(-2.0f, dot1, qsq + c1.w);                    \
            if (d0 <= gate) DO_INSERT(d0, p)                                   \
            if (d1 <= gate) DO_INSERT(d1, p + 4)                               \
        }                                                                      \
        if (p < (PB)) {                                                        \
            const float4 c0 = sp[p];                                           \
            const float dot0 = fmaf(qz, c0.z, fmaf(qy, c0.y, qx * c0.x));      \
            const float d0 = fmaf(-2.0f, dot0, qsq + c0.w);                    \
            if (d0 <= gate) DO_INSERT(d0, p)                                   \
        }                                                                      \
    }

#define REFRESH_UB()                                                           \
    {                                                                          \
        float m4v = mn[3];                                                     \
        m4v = fmaxf(m4v, __shfl_xor_sync(gmask, m4v, 1));                      \
        m4v = fmaxf(m4v, __shfl_xor_sync(gmask, m4v, 2));                      \
        float tmn = thr;                                                       \
        tmn = fminf(tmn, __shfl_xor_sync(gmask, tmn, 1));                      \
        tmn = fminf(tmn, __shfl_xor_sync(gmask, tmn, 2));                      \
        ub16 = fminf(m4v, tmn);                                                \
        gate = fminf(thr, ub16);                                               \
    }

#define COUNT_BELOW(BK, CNT)                                                   \
    {                                                                          \
        int c_ = 0;                                                            \
        _Pragma("unroll")                                                      \
        for (int j = 0; j < KK; j++) c_ += (keys[j] < (BK)) ? 1 : 0;           \
        c_ += __shfl_xor_sync(gmask, c_, 1);                                   \
        c_ += __shfl_xor_sync(gmask, c_, 2);                                   \
        (CNT) = c_;                                                            \
    }

    bool done = false;
    for (int R = 0; R <= GRID - 1 && !done; ++R) {
        const int z0 = max(cz - R, 0), z1 = min(cz + R, GRID - 1);
        const int y0 = max(cy - R, 0), y1 = min(cy + R, GRID - 1);
        const int x0 = max(cx - R, 0), x1 = min(cx + R, GRID - 1);
        // mid-ring termination key (valid for R>=2): unscanned >= (R-1)*CS
        u64 midbk = 0;
        if (R >= 2) {
            const float mb = (float)(R - 1) * CS;
            const float mbd = mb * mb * 0.9999f;
            unsigned sb = __float_as_uint(mbd);
            sb ^= (unsigned)((int)sb >> 31) | 0x80000000u;
            midbk = (u64)sb << 32;
        }
        for (int z = z0; z <= z1 && !done; z++) {
            const int az = z - cz;
            const float fz = (az < 0) ? (qz - (float)(z + 1) * CS)
                                      : ((az > 0) ? ((float)z * CS - qz) : 0.f);
            const float fz2 = fz * fz;
            for (int y = y0; y <= y1 && !done; y++) {
                const int ay = y - cy;
                const float fy = (ay < 0) ? (qy - (float)(y + 1) * CS)
                                          : ((ay > 0) ? ((float)y * CS - qy) : 0.f);
                const float ryz = fmaf(fy, fy, fz2);
                const int m2 = max(abs(az), abs(ay));
                const int rowbase = (z * GRID + y) * GRID;
                bool scanned = false;
                if (m2 == R) {
                    // whole row on the ring (x-range spans cx => fx = 0)
                    if (ryz <= ub16) {
                        const int pa = st[rowbase + x0];
                        const int pb = st[rowbase + x1 + 1];
                        SCAN_RANGE(pa, pb)
                        scanned = true;
                    }
                } else {
                    const int xl = cx - R, xr = cx + R;
                    if (xl >= 0) {
                        const float fx = qx - (float)(xl + 1) * CS;
                        if (fmaf(fx, fx, ryz) <= ub16) {
                            const int pa = st[rowbase + xl];
                            const int pb = st[rowbase + xl + 1];
                            SCAN_RANGE(pa, pb)
                            scanned = true;
                        }
                    }
                    if (xr <= GRID - 1) {
                        const float fx = (float)xr * CS - qx;
                        if (fmaf(fx, fx, ryz) <= ub16) {
                            const int pa = st[rowbase + xr];
                            const int pb = st[rowbase + xr + 1];
                            SCAN_RANGE(pa, pb)
                            scanned = true;
                        }
                    }
                }
                if (scanned) {        // group-uniform condition
                    REFRESH_UB()
                    if (R >= 2) {
                        int cnt;
                        COUNT_BELOW(midbk, cnt)
                        if (cnt >= KK) done = true;
                    }
                }
            }
        }
        if (!done) {
            // full-ring termination: unscanned cells >= R*CS away
            const float bound = (float)R * CS;
            const float bd = bound * bound * 0.9999f;
            unsigned sb = __float_as_uint(bd);
            sb ^= (unsigned)((int)sb >> 31) | 0x80000000u;
            const u64 bk = (u64)sb << 32;
            int cnt;
            COUNT_BELOW(bk, cnt)
            if (cnt >= KK) done = true;
        }
    }
#undef SCAN_RANGE
#undef DO_INSERT
#undef REFRESH_UB
#undef COUNT_BELOW

    // per-thread bitonic sort of the 16 keys (ascending)
#pragma unroll
    for (int kk2 = 2; kk2 <= KK; kk2 <<= 1) {
#pragma unroll
        for (int j = kk2 >> 1; j > 0; j >>= 1) {
#pragma unroll
            for (int i = 0; i < KK; i++) {
                if ((i & j) == 0) {
                    const int l = i | j;
                    const bool up = ((i & kk2) == 0);
                    const u64 lo = u64min(keys[i], keys[l]);
                    const u64 hi = u64max(keys[i], keys[l]);
                    keys[i] = up ? lo : hi;
                    keys[l] = up ? hi : lo;
                }
            }
        }
    }

    // exact merge: two bitonic stages (partners xor 1, xor 2)
#pragma unroll
    for (int stage = 0; stage < 2; stage++) {
        const int px = 1 << stage;
        u64 m[KK];
#pragma unroll
        for (int i = 0; i < KK; i++) {
            const u64 pk = __shfl_xor_sync(gmask, keys[KK - 1 - i], px);
            m[i] = u64min(keys[i], pk);   // 16 smallest of union, bitonic order
        }
#pragma unroll
        for (int s = 8; s >= 1; s >>= 1) {
#pragma unroll
            for (int i = 0; i < KK; i++) {
                if ((i & s) == 0) {
                    const u64 lo = u64min(m[i], m[i + s]);
                    const u64 hi = u64max(m[i], m[i + s]);
                    m[i] = lo; m[i + s] = hi;
                }
            }
        }
#pragma unroll
        for (int i = 0; i < KK; i++) keys[i] = m[i];
    }
    if (parity == 0) {
        const int q = sidx[slot];
        int* outp = g_knn + ((size_t)b * NN + q) * KK;
#pragma unroll
        for (int j = 0; j < KK; j++) outp[j] = (int)(keys[j] & 0xFFFFFFFFu);
    }
}

// ---------------------------------------------------------------------------
// Fused gather + collapsed-affine evaluation:
//   out_sum = W*s1 + C1,  pool = max_k g_k[:64],  aggr = W*s2 + C2
// One warp per point; sums accumulate in registers during the gather.
// ---------------------------------------------------------------------------
__device__ __forceinline__ void F2(u64& d, u64 a, u64 b) {
    asm("fma.rn.f32x2 %0, %1, %2, %0;" : "+l"(d) : "l"(a), "l"(b));
}
__device__ __forceinline__ float HADD(u64 v) {
    return __uint_as_float((unsigned)v) + __uint_as_float((unsigned)(v >> 32));
}
#define LD4(p)  (*reinterpret_cast<const float4*>(p))
#define LDU2(p) (*reinterpret_cast<const ulonglong2*>(p))

__global__ __launch_bounds__(256) void mlp2_kernel(
    const float* __restrict__ pf, const float* __restrict__ coords,
    const float* __restrict__ aggr_w, float* __restrict__ out)
{
    __shared__ __align__(16) float s_W[COUT * 68];
    __shared__ float s_C1[COUT], s_C2[COUT], s_u[KK];
    __shared__ __align__(16) float s_s[8][2][68];

    const int tid  = threadIdx.x;
    const int lane = tid & 31;
    const int w    = tid >> 5;

    for (int i = tid; i < COUT * 68; i += 256) s_W[i] = g_W[i];
    if (tid < 64) s_C1[tid] = g_C1[tid];
    else if (tid < 128) s_C2[tid - 64] = g_C2[tid - 64];
    else if (tid < 144) s_u[tid - 128] = aggr_w[tid - 128];
    __syncthreads();

    const int gp = blockIdx.x * 8 + w;
    const int b  = gp >> 13;
    const float* pfb = pf + (size_t)b * NN * CIN;
    const float* cob = coords + (size_t)b * NN * 3;

    const int nk = g_knn[(size_t)gp * KK + (lane & 15)];
    const int cc = (lane & 15) * 4;

    float4 pool = make_float4(-3.4e38f, -3.4e38f, -3.4e38f, -3.4e38f);
    float4 a1 = make_float4(0.f, 0.f, 0.f, 0.f);
    float4 a2 = a1;
#pragma unroll
    for (int k2 = 0; k2 < KK; k2 += 2) {
        const int k = k2 + (lane >> 4);
        const int m = __shfl_sync(0xffffffffu, nk, k);
        const float u = s_u[k];
        const float4 v = LD4(pfb + (size_t)m * CIN + cc);
        pool.x = fmaxf(pool.x, v.x); pool.y = fmaxf(pool.y, v.y);
        pool.z = fmaxf(pool.z, v.z); pool.w = fmaxf(pool.w, v.w);
        a1.x += v.x; a1.y += v.y; a1.z += v.z; a1.w += v.w;
        a2.x = fmaf(u, v.x, a2.x); a2.y = fmaf(u, v.y, a2.y);
        a2.z = fmaf(u, v.z, a2.z); a2.w = fmaf(u, v.w, a2.w);
    }
    // combine the two k-halves (lane <-> lane+16)
    pool.x = fmaxf(pool.x, __shfl_xor_sync(0xffffffffu, pool.x, 16));
    pool.y = fmaxf(pool.y, __shfl_xor_sync(0xffffffffu, pool.y, 16));
    pool.z = fmaxf(pool.z, __shfl_xor_sync(0xffffffffu, pool.z, 16));
    pool.w = fmaxf(pool.w, __shfl_xor_sync(0xffffffffu, pool.w, 16));
    a1.x += __shfl_xor_sync(0xffffffffu, a1.x, 16);
    a1.y += __shfl_xor_sync(0xffffffffu, a1.y, 16);
    a1.z += __shfl_xor_sync(0xffffffffu, a1.z, 16);
    a1.w += __shfl_xor_sync(0xffffffffu, a1.w, 16);
    a2.x += __shfl_xor_sync(0xffffffffu, a2.x, 16);
    a2.y += __shfl_xor_sync(0xffffffffu, a2.y, 16);
    a2.z += __shfl_xor_sync(0xffffffffu, a2.z, 16);
    a2.w += __shfl_xor_sync(0xffffffffu, a2.w, 16);

    // relative-coord channel sums (channels 64..66)
    const int m0 = __shfl_sync(0xffffffffu, nk, 0);
    const float c0x = cob[(size_t)m0 * 3 + 0];
    const float c0y = cob[(size_t)m0 * 3 + 1];
    const float c0z = cob[(size_t)m0 * 3 + 2];
    float dx = 0.f, dy = 0.f, dz = 0.f, ex = 0.f, ey = 0.f, ez = 0.f;
    if (lane < KK) {
        const float* cp = cob + (size_t)nk * 3;
        dx = cp[0] - c0x; dy = cp[1] - c0y; dz = cp[2] - c0z;
        const float u = s_u[lane];
        ex = u * dx; ey = u * dy; ez = u * dz;
    }
#pragma unroll
    for (int s = 8; s >= 1; s >>= 1) {
        dx += __shfl_xor_sync(0xffffffffu, dx, s);
        dy += __shfl_xor_sync(0xffffffffu, dy, s);
        dz += __shfl_xor_sync(0xffffffffu, dz, s);
        ex += __shfl_xor_sync(0xffffffffu, ex, s);
        ey += __shfl_xor_sync(0xffffffffu, ey, s);
        ez += __shfl_xor_sync(0xffffffffu, ez, s);
    }

    if (lane < 16) {
        *reinterpret_cast<float4*>(&s_s[w][0][cc]) = a1;
        *reinterpret_cast<float4*>(&s_s[w][1][cc]) = a2;
    }
    if (lane == 0) {
        s_s[w][0][64] = dx; s_s[w][0][65] = dy; s_s[w][0][66] = dz; s_s[w][0][67] = 0.f;
        s_s[w][1][64] = ex; s_s[w][1][65] = ey; s_s[w][1][66] = ez; s_s[w][1][67] = 0.f;
    }
    __syncwarp();

    // two 64x67 matvecs: lane handles outputs (lane, lane+32) for s1 and s2
    u64 A1 = 0, B1 = 0, A2 = 0, B2 = 0;
#pragma unroll
    for (int c = 0; c < 68; c += 4) {
        const ulonglong2 wA = LDU2(s_W + lane * 68 + c);
        const ulonglong2 wB = LDU2(s_W + (lane + 32) * 68 + c);
        const ulonglong2 x1 = LDU2(&s_s[w][0][c]);
        const ulonglong2 x2 = LDU2(&s_s[w][1][c]);
        F2(A1, x1.x, wA.x); F2(A1, x1.y, wA.y);
        F2(B1, x1.x, wB.x); F2(B1, x1.y, wB.y);
        F2(A2, x2.x, wA.x); F2(A2, x2.y, wA.y);
        F2(B2, x2.x, wB.x); F2(B2, x2.y, wB.y);
    }

    float* op = out + (size_t)gp * 192;
    op[lane]        = HADD(A1) + s_C1[lane];
    op[32 + lane]   = HADD(B1) + s_C1[lane + 32];
    op[128 + lane]  = HADD(A2) + s_C2[lane];
    op[160 + lane]  = HADD(B2) + s_C2[lane + 32];
    if (lane < 16) *reinterpret_cast<float4*>(op + 64 + cc) = pool;
}

// ---------------------------------------------------------------------------
extern "C" void kernel_launch(void* const* d_in, const int* in_sizes, int n_in,
                              void* d_out, int out_size) {
    const float* pf     = (const float*)d_in[0];
    const float* coords = (const float*)d_in[1];
    const float* w1     = (const float*)d_in[2];
    const float* b1     = (const float*)d_in[3];
    const float* w2     = (const float*)d_in[4];
    const float* b2     = (const float*)d_in[5];
    const float* w3     = (const float*)d_in[6];
    const float* b3     = (const float*)d_in[7];
    const float* aw     = (const float*)d_in[8];
    const float* ab     = (const float*)d_in[9];
    float* out = (float*)d_out;

    knn_bin_pre<<<65, 256>>>(coords, w1, b1, w2, b2, w3, b3, aw, ab);
    knn_scan<<<BB, NCELL / 2>>>();
    knn_scatter<<<BB * NN / 256, 256>>>(coords);
    knn_main<<<BB * NN * SLC / 128, 128>>>();
    mlp2_kernel<<<(BB * NN) / 8, 256>>>(pf, coords, aw, out);
}